// round 13
// baseline (speedup 1.0000x reference)
#include <cuda_runtime.h>
#include <cuda_fp16.h>
#include <cstdint>
#include <math.h>

// ---------------- problem constants ----------------
#define BB 32
#define DD 512
#define KK 64
#define TNP 64              // pixels per tile
#define NNPIX 3136
#define NTILES 49           // 3136/64
#define NJOBS (BB * NTILES) // 1568
#define GRID 152            // one CTA per SM
#define THREADS 512

// ---------------- smem byte offsets ----------------
// ws  : fp16 [64][520]  (1040B rows)                 66560
// xdn : fp16 2 x [512][128B] XOR-swizzled            131072
// at  : f32  [64][68]                                 17408
// akp : fp16 [64] rows of 144B                         9216
// asr : f32  [8][72]                                   2304
#define WS_OFF    0
#define XDN_OFF   66560
#define XBUF_BYTES 65536
#define AT_OFF    (XDN_OFF + 2 * XBUF_BYTES)   // 197632
#define AKP_OFF   (AT_OFF + 17408)             // 215040
#define ASR_OFF   (AKP_OFF + 9216)             // 224256
#define SMEM_BYTES (ASR_OFF + 2304 + 16)       // 226576

// ---------------- device scratch ----------------
__device__ float g_vsum[BB * DD * KK];          // [b][d][k] (atomic)
__device__ float g_asum[BB * KK];               // [b][k] (atomic)
__device__ float g_red[BB * 16 * KK];           // sumsq slices [b][slice][k]

// m16n8k16 fp16 mma, f32 accum.
static __device__ __forceinline__ void mma_f16(float c[4],
        uint32_t a0, uint32_t a1, uint32_t a2, uint32_t a3,
        uint32_t b0, uint32_t b1) {
    asm volatile(
        "mma.sync.aligned.m16n8k16.row.col.f32.f16.f16.f32 "
        "{%0,%1,%2,%3}, {%4,%5,%6,%7}, {%8,%9}, {%0,%1,%2,%3};"
        : "+f"(c[0]), "+f"(c[1]), "+f"(c[2]), "+f"(c[3])
        : "r"(a0), "r"(a1), "r"(a2), "r"(a3), "r"(b0), "r"(b1));
}
#define LDSM4(r0, r1, r2, r3, addr) \
    asm volatile("ldmatrix.sync.aligned.m8n8.x4.shared.b16 {%0,%1,%2,%3}, [%4];" \
        : "=r"(r0), "=r"(r1), "=r"(r2), "=r"(r3) : "r"(addr))
#define LDSM4T(r0, r1, r2, r3, addr) \
    asm volatile("ldmatrix.sync.aligned.m8n8.x4.trans.shared.b16 {%0,%1,%2,%3}, [%4];" \
        : "=r"(r0), "=r"(r1), "=r"(r2), "=r"(r3) : "r"(addr))

static __device__ __forceinline__ uint32_t smem_u32(const void* p) {
    uint32_t a;
    asm("{ .reg .u64 t; cvta.to.shared.u64 t, %1; cvt.u32.u64 %0, t; }" : "=r"(a) : "l"(p));
    return a;
}
static __device__ __forceinline__ uint2 cvt_f4h(float4 v) {
    __half2 h0 = __floats2half2_rn(v.x, v.y);
    __half2 h1 = __floats2half2_rn(v.z, v.w);
    uint2 u;
    u.x = *(uint32_t*)&h0;
    u.y = *(uint32_t*)&h1;
    return u;
}

// ---------------------------------------------------------------------------
__global__ void zero_kernel() {
    int i = blockIdx.x * 256 + threadIdx.x;
    float4 z = {0.f, 0.f, 0.f, 0.f};
    if (i < BB * DD * KK / 4) ((float4*)g_vsum)[i] = z;
    if (i < BB * KK / 4)      ((float4*)g_asum)[i] = z;
}

// ---------------------------------------------------------------------------
// Fused kernel. grid = 152, block = 512, 1 CTA/SM.
// xdn double-buffered; the whole next tile is prefetched with two
// phase-bracketed LDG-at-start / STS-at-end groups (GEMM1: lower half,
// GEMM2: upper half). No dedicated fill phase; 3 barriers/tile.
// ---------------------------------------------------------------------------
__global__ void __launch_bounds__(THREADS, 1) fused_kernel(
    const float* __restrict__ x,      // [B, D, N]
    const float* __restrict__ w,      // [K, D]
    const float* __restrict__ bias)   // [K]
{
    extern __shared__ char sm[];
    __half* ws    = (__half*)(sm + WS_OFF);
    char*   xdn   = sm + XDN_OFF;               // 2 swizzled fp16 buffers
    float*  at    = (float*)(sm + AT_OFF);      // [64][68]
    char*   akp   = sm + AKP_OFF;               // fp16 [64] rows of 144B
    float*  asred = (float*)(sm + ASR_OFF);     // [8][72]
    const uint32_t xdn_u = smem_u32(xdn);
    const uint32_t ws_u  = smem_u32(ws);
    const uint32_t akp_u = smem_u32(akp);

    const int tid  = threadIdx.x;
    const int wid  = tid >> 5;
    const int lane = tid & 31;
    const int g    = lane >> 2;
    const int tg   = lane & 3;

    // ---- job range: 48 CTAs get 11 jobs, 104 get 10 --------------------------
    const int cta  = blockIdx.x;
    const int job0 = cta * 10 + (cta < 48 ? cta : 48);
    const int job1 = job0 + 10 + (cta < 48 ? 1 : 0);

    // ---- loader lane constants (128B swizzled rows) --------------------------
    const int jj    = tid & 15;
    const int r0    = tid >> 4;
    const uint32_t sts_off = (uint32_t)r0 * 128
        + ((uint32_t)((jj >> 1) ^ (r0 & 7)) * 16 + (uint32_t)(jj & 1) * 8);

    // ---- GEMM1 mapping: m-tile = 16 px (wid&3), n = 16 k at n0 ---------------
    const int p0 = (wid & 3) * 16;
    const int n0 = (wid >> 2) * 16;
    const float bias_a0 = bias[n0 + 2 * tg];
    const float bias_a1 = bias[n0 + 2 * tg + 1];
    const float bias_b0 = bias[n0 + 8 + 2 * tg];
    const float bias_b1 = bias[n0 + 8 + 2 * tg + 1];
    const uint32_t lmA1_off = (uint32_t)((lane & 7) + (lane >> 4) * 8) * 128
        + (uint32_t)((((wid & 3) * 2 + ((lane >> 3) & 1)) ^ (lane & 7)) * 16);
    const uint32_t lmB1 = ws_u
        + (uint32_t)((n0 + (lane & 7) + (lane >> 4) * 8) * 1040
                     + ((lane >> 3) & 1) * 16);

    // ---- GEMM2 mapping (retile): warp tile = 32 k x 64 d ----------------------
    const int kbw = (wid & 1) * 32;
    const int dbw = (wid >> 1) * 64;
    const uint32_t lmA2_0 = akp_u
        + (uint32_t)((kbw + (lane & 15)) * 144 + (lane >> 4) * 16);
    const uint32_t lmA2_1 = lmA2_0 + 16 * 144;
    const uint32_t lmB2_row = (uint32_t)(dbw + (lane & 7) + (lane >> 4) * 8) * 128;
    const uint32_t lc  = lane & 7;
    const uint32_t hi2 = (lane >> 3) & 1;

    // ---- convert w -> fp16 ws once --------------------------------------------
#pragma unroll
    for (int r = 0; r < 16; ++r) {
        int idx = tid + r * THREADS;
        int k = idx >> 7;
        int j = idx & 127;
        float4 v = *(const float4*)(w + (size_t)k * DD + j * 4);
        uint2 u = cvt_f4h(v);
        *(uint2*)((char*)ws + k * 1040 + j * 8) = u;
    }

    // ---- prologue: fill buffer 0 with first job's tile -------------------------
    {
        int b0 = job0 / NTILES;
        int t0 = job0 - b0 * NTILES;
        const float* xg0 = x + (size_t)b0 * DD * NNPIX;
#pragma unroll
        for (int i = 0; i < 16; ++i) {
            float4 v = *(const float4*)(xg0 + (size_t)(i * 32 + r0) * NNPIX
                                        + t0 * TNP + jj * 4);
            *(uint2*)(xdn + sts_off + i * 4096) = cvt_f4h(v);
        }
    }

    float c2[2][8][4];
    int tot = 0;
    int jg = job0;
    while (jg < job1) {
        const int bcur = jg / NTILES;
        const int seg_end = min(job1, (bcur + 1) * NTILES);

#pragma unroll
        for (int kt = 0; kt < 2; ++kt)
#pragma unroll
            for (int j = 0; j < 8; ++j)
#pragma unroll
                for (int r = 0; r < 4; ++r) c2[kt][j][r] = 0.0f;
        float asum_acc = 0.0f;

        for (int lt = 0; jg < seg_end; ++jg, ++lt, ++tot) {
            const int t = jg - bcur * NTILES;
            const int cur = tot & 1;
            const uint32_t xcur_u  = xdn_u + (uint32_t)cur * XBUF_BYTES;
            const uint32_t xnxt_of = (uint32_t)(cur ^ 1) * XBUF_BYTES;
            const bool has_next = (jg + 1 < job1);
            const float* xgn = 0;
            int tn = 0;
            if (has_next) {
                int bn = (jg + 1) / NTILES;
                tn = (jg + 1) - bn * NTILES;
                xgn = x + (size_t)bn * DD * NNPIX;
            }

            __syncthreads();                   // (A) buf[cur] complete; akp/at/asred free

            if (lt > 0 && tid < KK) {
                float s = 0.0f;
#pragma unroll
                for (int i = 0; i < 8; ++i) s += asred[i * 72 + tid];
                asum_acc += s;
            }

            // ---- GEMM1 (buf[cur]) + lower-half-next prefetch -----------------
            {
                float4 pf[8];
                if (has_next) {
#pragma unroll
                    for (int i = 0; i < 8; ++i)
                        pf[i] = *(const float4*)(xgn + (size_t)(i * 32 + r0) * NNPIX
                                                 + tn * TNP + jj * 4);
                }
                float c1a[4] = {0.f, 0.f, 0.f, 0.f};
                float c1b[4] = {0.f, 0.f, 0.f, 0.f};
                const uint32_t a_base = xcur_u + lmA1_off;
#pragma unroll
                for (int ks = 0; ks < 32; ++ks) {
                    uint32_t a0, a1, a2, a3, b0, b1, b2, b3;
                    LDSM4T(a0, a1, a2, a3, a_base + (uint32_t)ks * 2048);
                    LDSM4(b0, b1, b2, b3, lmB1 + (uint32_t)ks * 32);
                    mma_f16(c1a, a0, a1, a2, a3, b0, b1);
                    mma_f16(c1b, a0, a1, a2, a3, b2, b3);
                }
                if (has_next) {
#pragma unroll
                    for (int i = 0; i < 8; ++i)
                        *(uint2*)(xdn + xnxt_of + sts_off + i * 4096) = cvt_f4h(pf[i]);
                }
                float* atp = at + (p0 + g) * 68;
                atp[n0 + 2 * tg]              = c1a[0] + bias_a0;
                atp[n0 + 2 * tg + 1]          = c1a[1] + bias_a1;
                atp[8 * 68 + n0 + 2 * tg]     = c1a[2] + bias_a0;
                atp[8 * 68 + n0 + 2 * tg + 1] = c1a[3] + bias_a1;
                atp[n0 + 8 + 2 * tg]              = c1b[0] + bias_b0;
                atp[n0 + 8 + 2 * tg + 1]          = c1b[1] + bias_b1;
                atp[8 * 68 + n0 + 8 + 2 * tg]     = c1b[2] + bias_b0;
                atp[8 * 68 + n0 + 8 + 2 * tg + 1] = c1b[3] + bias_b1;
            }
            __syncthreads();                   // (C) logits staged

            // ---- softmax over k per pixel --------------------------------------
#pragma unroll
            for (int pp = 0; pp < 4; ++pp) {
                int p = wid * 4 + pp;
                float v0 = at[p * 68 + lane];
                float v1 = at[p * 68 + lane + 32];
                float m = fmaxf(v0, v1);
#pragma unroll
                for (int off = 16; off > 0; off >>= 1)
                    m = fmaxf(m, __shfl_xor_sync(0xFFFFFFFFu, m, off));
                float e0 = __expf(v0 - m);
                float e1 = __expf(v1 - m);
                float s = e0 + e1;
#pragma unroll
                for (int off = 16; off > 0; off >>= 1)
                    s += __shfl_xor_sync(0xFFFFFFFFu, s, off);
                float inv = 1.0f / s;
                *(__half*)(akp + lane * 144 + p * 2)        = __float2half_rn(e0 * inv);
                *(__half*)(akp + (lane + 32) * 144 + p * 2) = __float2half_rn(e1 * inv);
            }
            __syncthreads();                   // (D) alpha ready

            // ---- asum partials ---------------------------------------------------
            {
                int k = tid & 63;
                int grp = tid >> 6;
                uint4 u = *(const uint4*)(akp + k * 144 + grp * 16);
                float2 f0 = __half22float2(*(__half2*)&u.x);
                float2 f1 = __half22float2(*(__half2*)&u.y);
                float2 f2 = __half22float2(*(__half2*)&u.z);
                float2 f3 = __half22float2(*(__half2*)&u.w);
                asred[grp * 72 + k] = (f0.x + f0.y) + (f1.x + f1.y)
                                    + (f2.x + f2.y) + (f3.x + f3.y);
            }

            // ---- GEMM2 (buf[cur]) + upper-half-next prefetch --------------------
            {
                float4 pf[8];
                if (has_next) {
#pragma unroll
                    for (int i = 0; i < 8; ++i)
                        pf[i] = *(const float4*)(xgn + (size_t)(256 + i * 32 + r0) * NNPIX
                                                 + tn * TNP + jj * 4);
                }
#pragma unroll
                for (int s = 0; s < 4; ++s) {
                    uint32_t aA0, aA1, aA2, aA3, aB0, aB1, aB2, aB3;
                    LDSM4(aA0, aA1, aA2, aA3, lmA2_0 + (uint32_t)s * 32);
                    LDSM4(aB0, aB1, aB2, aB3, lmA2_1 + (uint32_t)s * 32);
                    const uint32_t swoff = (((uint32_t)s * 2 + hi2) ^ lc) * 16;
                    const uint32_t bbase = xcur_u + lmB2_row + swoff;
#pragma unroll
                    for (int j2 = 0; j2 < 4; ++j2) {
                        uint32_t b0, b1, b2, b3;
                        LDSM4(b0, b1, b2, b3, bbase + (uint32_t)j2 * 2048);
                        mma_f16(c2[0][2 * j2],     aA0, aA1, aA2, aA3, b0, b1);
                        mma_f16(c2[0][2 * j2 + 1], aA0, aA1, aA2, aA3, b2, b3);
                        mma_f16(c2[1][2 * j2],     aB0, aB1, aB2, aB3, b0, b1);
                        mma_f16(c2[1][2 * j2 + 1], aB0, aB1, aB2, aB3, b2, b3);
                    }
                }
                if (has_next) {
#pragma unroll
                    for (int i = 0; i < 8; ++i)
                        *(uint2*)(xdn + xnxt_of + sts_off + (8 + i) * 4096) = cvt_f4h(pf[i]);
                }
            }
        }

        // ---- segment flush -----------------------------------------------------
        __syncthreads();                       // asred/last-tile readers done
        if (tid < KK) {
            float s = 0.0f;
#pragma unroll
            for (int i = 0; i < 8; ++i) s += asred[i * 72 + tid];
            atomicAdd(&g_asum[bcur * KK + tid], asum_acc + s);
        }

        // stage into the just-consumed buffer (the other holds the prefetch)
        float* stage = (float*)(xdn + (size_t)((tot - 1) & 1) * XBUF_BYTES); // [128][72]
        float* dstb = g_vsum + (size_t)bcur * DD * KK;
        const int dloc = ((wid >> 1) & 1) * 64;
        for (int chunk = 0; chunk < 4; ++chunk) {
            __syncthreads();
            if ((wid >> 2) == chunk) {
#pragma unroll
                for (int kt = 0; kt < 2; ++kt) {
                    int kcol = kbw + kt * 16 + g;
#pragma unroll
                    for (int j = 0; j < 8; ++j) {
                        int dl = dloc + j * 8 + 2 * tg;
                        stage[dl * 72 + kcol]           = c2[kt][j][0];
                        stage[(dl + 1) * 72 + kcol]     = c2[kt][j][1];
                        stage[dl * 72 + kcol + 8]       = c2[kt][j][2];
                        stage[(dl + 1) * 72 + kcol + 8] = c2[kt][j][3];
                    }
                }
            }
            __syncthreads();
            float* dst = dstb + (size_t)chunk * 128 * KK;
#pragma unroll
            for (int r = 0; r < 4; ++r) {
                int i = tid + r * THREADS;
                int dl = i >> 4;
                int k4 = (i & 15) * 4;
                float4 v = *(float4*)&stage[dl * 72 + k4];
                float* d4 = &dst[(size_t)dl * KK + k4];
                atomicAdd(d4 + 0, v.x);
                atomicAdd(d4 + 1, v.y);
                atomicAdd(d4 + 2, v.z);
                atomicAdd(d4 + 3, v.w);
            }
        }
    }
}

// ---------------------------------------------------------------------------
// Epilogue A: per-slice sumsq of y = vsum - centers*asum. grid (16, 32).
// ---------------------------------------------------------------------------
__global__ void reduce_ss_kernel(const float* __restrict__ centers) {
    const int sl = blockIdx.x;
    const int b  = blockIdx.y;
    const int k  = threadIdx.x & 63;
    const int dg = threadIdx.x >> 6;

    const float a = g_asum[b * KK + k];
    const float* vb = g_vsum + (size_t)b * DD * KK;

    float ss = 0.0f;
#pragma unroll
    for (int i = 0; i < 8; ++i) {
        int d = sl * 32 + dg * 8 + i;
        size_t o = (size_t)d * KK + k;
        float y = vb[o] - centers[o] * a;
        ss += y * y;
    }
    __shared__ float red[4][KK];
    red[dg][k] = ss;
    __syncthreads();
    if (threadIdx.x < KK)
        g_red[(b * 16 + sl) * KK + k] = red[0][k] + red[1][k] + red[2][k] + red[3][k];
}

// ---------------------------------------------------------------------------
// Epilogue B: recompute y, scale, store. grid (16, 32).
// Global norm after intra-normalization == sqrt(K)=8 -> fold 1/8.
// ---------------------------------------------------------------------------
__global__ void scale_kernel(const float* __restrict__ centers,
                             float* __restrict__ out) {
    const int sl = blockIdx.x;
    const int b  = blockIdx.y;
    __shared__ float cns[KK];
    __shared__ float asm_s[KK];
    if (threadIdx.x < KK) {
        float s = 0.0f;
#pragma unroll
        for (int j = 0; j < 16; ++j) s += g_red[(b * 16 + j) * KK + threadIdx.x];
        cns[threadIdx.x] = 0.125f * rsqrtf(s);
        asm_s[threadIdx.x] = g_asum[b * KK + threadIdx.x];
    }
    __syncthreads();

    const float* vb = g_vsum + (size_t)b * DD * KK + (size_t)sl * 32 * KK;
    const float* cb = centers + (size_t)sl * 32 * KK;
    float* ob = out + (size_t)b * DD * KK + (size_t)sl * 32 * KK;
#pragma unroll
    for (int r = 0; r < 2; ++r) {
        int i = threadIdx.x + r * 256;
        int k4 = (i & 15) * 4;
        float4 v = *(const float4*)(vb + (size_t)i * 4);
        float4 c = *(const float4*)(cb + (size_t)i * 4);
        v.x = (v.x - c.x * asm_s[k4])     * cns[k4];
        v.y = (v.y - c.y * asm_s[k4 + 1]) * cns[k4 + 1];
        v.z = (v.z - c.z * asm_s[k4 + 2]) * cns[k4 + 2];
        v.w = (v.w - c.w * asm_s[k4 + 3]) * cns[k4 + 3];
        *(float4*)(ob + (size_t)i * 4) = v;
    }
}

// ---------------------------------------------------------------------------
extern "C" void kernel_launch(void* const* d_in, const int* in_sizes, int n_in,
                              void* d_out, int out_size) {
    const float* x       = (const float*)d_in[0];
    const float* w       = (const float*)d_in[1];
    const float* bias    = (const float*)d_in[2];
    const float* centers = (const float*)d_in[3];
    float* out = (float*)d_out;

    cudaFuncSetAttribute(fused_kernel,
                         cudaFuncAttributeMaxDynamicSharedMemorySize, SMEM_BYTES);

    zero_kernel<<<(BB * DD * KK / 4 + 255) / 256, 256>>>();
    fused_kernel<<<GRID, THREADS, SMEM_BYTES>>>(x, w, bias);
    reduce_ss_kernel<<<dim3(16, BB), 256>>>(centers);
    scale_kernel<<<dim3(16, BB), 256>>>(centers, out);
}

// round 14
// speedup vs baseline: 1.3619x; 1.3619x over previous
#include <cuda_runtime.h>
#include <cuda_fp16.h>
#include <cstdint>
#include <math.h>

// ---------------- problem constants ----------------
#define BB 32
#define DD 512
#define KK 64
#define TNP 64              // pixels per tile
#define NNPIX 3136
#define NTILES 49           // 3136/64
#define CPB 4               // CTAs per batch
#define THREADS 512

// ---------------- smem byte offsets (R8 layout) ----------------
#define WS_OFF    0                        // fp16 [64][520]  (1040B rows)
#define XDN_OFF   66560                    // fp16 [512] rows of 144B
#define AT_OFF    (XDN_OFF + 73728)        // f32  [64][68]
#define AKP_OFF   (AT_OFF + 17408)         // fp16 [64] rows of 144B
#define ASR_OFF   (AKP_OFF + 9216)         // f32  [8][72]
#define SMEM_BYTES (ASR_OFF + 2304 + 16)   // 169232

// ---------------- device scratch ----------------
__device__ float g_part[BB * CPB * DD * KK];    // [cta][d][k]
__device__ float g_asum_part[BB * CPB * KK];    // [cta][k]
__device__ float g_y[BB * DD * KK];             // [b][d][k]
__device__ float g_red[BB * 16 * KK];           // sumsq slices [b][slice][k]

// m16n8k16 fp16 mma, f32 accum.
static __device__ __forceinline__ void mma_f16(float c[4],
        uint32_t a0, uint32_t a1, uint32_t a2, uint32_t a3,
        uint32_t b0, uint32_t b1) {
    asm volatile(
        "mma.sync.aligned.m16n8k16.row.col.f32.f16.f16.f32 "
        "{%0,%1,%2,%3}, {%4,%5,%6,%7}, {%8,%9}, {%0,%1,%2,%3};"
        : "+f"(c[0]), "+f"(c[1]), "+f"(c[2]), "+f"(c[3])
        : "r"(a0), "r"(a1), "r"(a2), "r"(a3), "r"(b0), "r"(b1));
}
#define LDSM4(r0, r1, r2, r3, addr) \
    asm volatile("ldmatrix.sync.aligned.m8n8.x4.shared.b16 {%0,%1,%2,%3}, [%4];" \
        : "=r"(r0), "=r"(r1), "=r"(r2), "=r"(r3) : "r"(addr))
#define LDSM4T(r0, r1, r2, r3, addr) \
    asm volatile("ldmatrix.sync.aligned.m8n8.x4.trans.shared.b16 {%0,%1,%2,%3}, [%4];" \
        : "=r"(r0), "=r"(r1), "=r"(r2), "=r"(r3) : "r"(addr))

static __device__ __forceinline__ uint32_t smem_u32(const void* p) {
    uint32_t a;
    asm("{ .reg .u64 t; cvta.to.shared.u64 t, %1; cvt.u32.u64 %0, t; }" : "=r"(a) : "l"(p));
    return a;
}
static __device__ __forceinline__ uint2 cvt_f4h(float4 v) {
    __half2 h0 = __floats2half2_rn(v.x, v.y);
    __half2 h1 = __floats2half2_rn(v.z, v.w);
    uint2 u;
    u.x = *(uint32_t*)&h0;
    u.y = *(uint32_t*)&h1;
    return u;
}

// ---------------------------------------------------------------------------
// Fused kernel. grid = 128 (b*4+q), block = 512, 1 CTA/SM.
// R8 schedule/loading; GEMM2 warp tile = 32k x 64d retile. (Best: R11.)
// ---------------------------------------------------------------------------
__global__ void __launch_bounds__(THREADS, 1) fused_kernel(
    const float* __restrict__ x,      // [B, D, N]
    const float* __restrict__ w,      // [K, D]
    const float* __restrict__ bias)   // [K]
{
    extern __shared__ char sm[];
    __half* ws    = (__half*)(sm + WS_OFF);
    char*   xdn   = sm + XDN_OFF;               // fp16 [512] rows of 144B
    float*  at    = (float*)(sm + AT_OFF);      // [64][68]
    char*   akp   = sm + AKP_OFF;               // fp16 [64] rows of 144B
    float*  asred = (float*)(sm + ASR_OFF);     // [8][72]
    const uint32_t xdn_u = smem_u32(xdn);
    const uint32_t ws_u  = smem_u32(ws);
    const uint32_t akp_u = smem_u32(akp);

    const int tid  = threadIdx.x;
    const int wid  = tid >> 5;
    const int lane = tid & 31;
    const int g    = lane >> 2;
    const int tg   = lane & 3;
    const int b    = blockIdx.x >> 2;
    const int q    = blockIdx.x & 3;

    // GEMM1: m-tile = 16 px (wid&3), n = 2 center-octets at n0
    const int p0 = (wid & 3) * 16;
    const int n0 = (wid >> 2) * 16;
    const float bias_a0 = bias[n0 + 2 * tg];
    const float bias_a1 = bias[n0 + 2 * tg + 1];
    const float bias_b0 = bias[n0 + 8 + 2 * tg];
    const float bias_b1 = bias[n0 + 8 + 2 * tg + 1];
    // A (x^T) via ldmatrix.x4.trans
    const uint32_t lmA1 = xdn_u
        + (uint32_t)(((lane >> 4) * 8 + (lane & 7)) * 144
                     + (p0 + ((lane >> 3) & 1) * 8) * 2);
    // B (w) via ldmatrix.x4
    const uint32_t lmB1 = ws_u
        + (uint32_t)((n0 + (lane & 7) + (lane >> 4) * 8) * 1040
                     + ((lane >> 3) & 1) * 16);

    // GEMM2 (retile): warp tile = 32 centers (wid&1) x 64 d ((wid>>1)*64)
    const int kbw = (wid & 1) * 32;
    const int dbw = (wid >> 1) * 64;
    const uint32_t lmA2_0 = akp_u
        + (uint32_t)((kbw + (lane & 15)) * 144 + (lane >> 4) * 16);
    const uint32_t lmA2_1 = lmA2_0 + 16 * 144;
    const uint32_t lmB2 = xdn_u
        + (uint32_t)((dbw + (lane & 7) + (lane >> 4) * 8) * 144
                     + ((lane >> 3) & 1) * 16);

    // ---- convert w -> fp16 ws once ------------------------------------------
#pragma unroll
    for (int r = 0; r < 16; ++r) {
        int idx = tid + r * THREADS;
        int k = idx >> 7;
        int j = idx & 127;
        float4 v = *(const float4*)(w + (size_t)k * DD + j * 4);
        uint2 u = cvt_f4h(v);
        *(uint2*)((char*)ws + k * 1040 + j * 8) = u;
    }

    // persistent vlad^T accumulators [2 k-tiles][8 d-octets][4]
    float c2[2][8][4];
#pragma unroll
    for (int kt = 0; kt < 2; ++kt)
#pragma unroll
        for (int j = 0; j < 8; ++j)
#pragma unroll
            for (int r = 0; r < 4; ++r) c2[kt][j][r] = 0.0f;

    float asum_acc = 0.0f;
    const float* xg = x + (size_t)b * DD * NNPIX;
    const int jj = tid & 15;
    const int r0 = tid >> 4;

    // ---- prologue prefetch: first tile, rows 256-511 -------------------------
    float4 pf[8];
#pragma unroll
    for (int i = 0; i < 8; ++i)
        pf[i] = *(const float4*)(xg + (size_t)(256 + r0 + i * 32) * NNPIX
                                 + q * TNP + jj * 4);

    int lt = 0;
    for (int t = q; t < NTILES; t += CPB, ++lt) {
        __syncthreads();                       // (A) prev consumers of xdn/akp done

        if (lt > 0 && tid < KK) {
            float s = 0.0f;
#pragma unroll
            for (int i = 0; i < 8; ++i) s += asred[i * 72 + tid];
            asum_acc += s;
        }

        // ---- fill xdn: half2 from prefetch regs, half1 synchronous ----------
#pragma unroll
        for (int i = 0; i < 8; ++i) {
            int r = 256 + r0 + i * 32;
            uint2 u = cvt_f4h(pf[i]);
            *(uint2*)(xdn + r * 144 + jj * 8) = u;
        }
#pragma unroll
        for (int i = 0; i < 8; ++i) {
            int r = r0 + i * 32;
            float4 v = *(const float4*)(xg + (size_t)r * NNPIX + t * TNP + jj * 4);
            uint2 u = cvt_f4h(v);
            *(uint2*)(xdn + r * 144 + jj * 8) = u;
        }
        __syncthreads();                       // (B) xdn ready

        // ---- GEMM1: logits^T[64px][64k] = x^T @ w^T ---------------------------
        {
            float c1a[4] = {0.f, 0.f, 0.f, 0.f};
            float c1b[4] = {0.f, 0.f, 0.f, 0.f};
#pragma unroll
            for (int ks = 0; ks < 32; ++ks) {
                uint32_t a0, a1, a2, a3, b0, b1, b2, b3;
                LDSM4T(a0, a1, a2, a3, lmA1 + (uint32_t)ks * 2304);
                LDSM4(b0, b1, b2, b3, lmB1 + (uint32_t)ks * 32);
                mma_f16(c1a, a0, a1, a2, a3, b0, b1);
                mma_f16(c1b, a0, a1, a2, a3, b2, b3);
            }
            float* atp = at + (p0 + g) * 68;
            atp[n0 + 2 * tg]              = c1a[0] + bias_a0;
            atp[n0 + 2 * tg + 1]          = c1a[1] + bias_a1;
            atp[8 * 68 + n0 + 2 * tg]     = c1a[2] + bias_a0;
            atp[8 * 68 + n0 + 2 * tg + 1] = c1a[3] + bias_a1;
            atp[n0 + 8 + 2 * tg]              = c1b[0] + bias_b0;
            atp[n0 + 8 + 2 * tg + 1]          = c1b[1] + bias_b1;
            atp[8 * 68 + n0 + 8 + 2 * tg]     = c1b[2] + bias_b0;
            atp[8 * 68 + n0 + 8 + 2 * tg + 1] = c1b[3] + bias_b1;
        }
        __syncthreads();                       // (C) logits staged

        // ---- softmax over k per pixel -----------------------------------------
#pragma unroll
        for (int pp = 0; pp < 4; ++pp) {
            int p = wid * 4 + pp;
            float v0 = at[p * 68 + lane];
            float v1 = at[p * 68 + lane + 32];
            float m = fmaxf(v0, v1);
#pragma unroll
            for (int off = 16; off > 0; off >>= 1)
                m = fmaxf(m, __shfl_xor_sync(0xFFFFFFFFu, m, off));
            float e0 = __expf(v0 - m);
            float e1 = __expf(v1 - m);
            float s = e0 + e1;
#pragma unroll
            for (int off = 16; off > 0; off >>= 1)
                s += __shfl_xor_sync(0xFFFFFFFFu, s, off);
            float inv = 1.0f / s;
            *(__half*)(akp + lane * 144 + p * 2)        = __float2half_rn(e0 * inv);
            *(__half*)(akp + (lane + 32) * 144 + p * 2) = __float2half_rn(e1 * inv);
        }
        __syncthreads();                       // (D) alpha ready

        // ---- prefetch next tile rows 256-511 (lands during GEMM2) ------------
        if (t + CPB < NTILES) {
#pragma unroll
            for (int i = 0; i < 8; ++i)
                pf[i] = *(const float4*)(xg + (size_t)(256 + r0 + i * 32) * NNPIX
                                         + (t + CPB) * TNP + jj * 4);
        }

        // ---- asum partials ------------------------------------------------------
        {
            int k = tid & 63;
            int grp = tid >> 6;
            uint4 u = *(const uint4*)(akp + k * 144 + grp * 16);
            float2 f0 = __half22float2(*(__half2*)&u.x);
            float2 f1 = __half22float2(*(__half2*)&u.y);
            float2 f2 = __half22float2(*(__half2*)&u.z);
            float2 f3 = __half22float2(*(__half2*)&u.w);
            asred[grp * 72 + k] = (f0.x + f0.y) + (f1.x + f1.y)
                                + (f2.x + f2.y) + (f3.x + f3.y);
        }

        // ---- GEMM2 (retile): vlad^T[32k x 64d per warp] += alpha @ x^T --------
#pragma unroll
        for (int s = 0; s < 4; ++s) {
            uint32_t aA0, aA1, aA2, aA3, aB0, aB1, aB2, aB3;
            LDSM4(aA0, aA1, aA2, aA3, lmA2_0 + (uint32_t)s * 32);
            LDSM4(aB0, aB1, aB2, aB3, lmA2_1 + (uint32_t)s * 32);
#pragma unroll
            for (int j2 = 0; j2 < 4; ++j2) {
                uint32_t b0, b1, b2, b3;
                LDSM4(b0, b1, b2, b3, lmB2 + (uint32_t)(j2 * 2304 + s * 32));
                mma_f16(c2[0][2 * j2],     aA0, aA1, aA2, aA3, b0, b1);
                mma_f16(c2[0][2 * j2 + 1], aA0, aA1, aA2, aA3, b2, b3);
                mma_f16(c2[1][2 * j2],     aB0, aB1, aB2, aB3, b0, b1);
                mma_f16(c2[1][2 * j2 + 1], aB0, aB1, aB2, aB3, b2, b3);
            }
        }
    }

    __syncthreads();
    if (tid < KK) {
        float s = 0.0f;
#pragma unroll
        for (int i = 0; i < 8; ++i) s += asred[i * 72 + tid];
        g_asum_part[blockIdx.x * KK + tid] = asum_acc + s;
    }

    // ---- epilogue: transpose-stage vlad^T -> g_part[cta][d][k] ----------------
    float* stage = (float*)xdn;                // [128][72] f32
    float* dstb = g_part + (size_t)blockIdx.x * DD * KK;
    const int dloc = ((wid >> 1) & 1) * 64;    // d offset within 128-row chunk
    for (int chunk = 0; chunk < 4; ++chunk) {
        __syncthreads();
        if ((wid >> 2) == chunk) {
#pragma unroll
            for (int kt = 0; kt < 2; ++kt) {
                int kcol = kbw + kt * 16 + g;
#pragma unroll
                for (int j = 0; j < 8; ++j) {
                    int dl = dloc + j * 8 + 2 * tg;
                    stage[dl * 72 + kcol]           = c2[kt][j][0];
                    stage[(dl + 1) * 72 + kcol]     = c2[kt][j][1];
                    stage[dl * 72 + kcol + 8]       = c2[kt][j][2];
                    stage[(dl + 1) * 72 + kcol + 8] = c2[kt][j][3];
                }
            }
        }
        __syncthreads();
        float* dst = dstb + (size_t)chunk * 128 * KK;
#pragma unroll
        for (int r = 0; r < 4; ++r) {
            int i = tid + r * THREADS;
            int dl = i >> 4;
            int k4 = (i & 15) * 4;
            float4 v = *(float4*)&stage[dl * 72 + k4];
            *(float4*)&dst[(size_t)dl * KK + k4] = v;
        }
    }
}

// ---------------------------------------------------------------------------
// Epilogue A: y = sum_q part - centers*asum ; per-slice sumsq partials.
// ---------------------------------------------------------------------------
__global__ void reduce_y_kernel(const float* __restrict__ centers) {
    const int sl = blockIdx.x;
    const int b  = blockIdx.y;
    const int k  = threadIdx.x & 63;
    const int dg = threadIdx.x >> 6;

    float a = g_asum_part[(b * 4 + 0) * KK + k]
            + g_asum_part[(b * 4 + 1) * KK + k]
            + g_asum_part[(b * 4 + 2) * KK + k]
            + g_asum_part[(b * 4 + 3) * KK + k];

    const float* p0 = g_part + (size_t)(b * 4 + 0) * DD * KK;
    const float* p1 = g_part + (size_t)(b * 4 + 1) * DD * KK;
    const float* p2 = g_part + (size_t)(b * 4 + 2) * DD * KK;
    const float* p3 = g_part + (size_t)(b * 4 + 3) * DD * KK;
    float* yb = g_y + (size_t)b * DD * KK;

    float ss = 0.0f;
#pragma unroll
    for (int i = 0; i < 8; ++i) {
        int d = sl * 32 + dg * 8 + i;
        size_t o = (size_t)d * KK + k;
        float y = p0[o] + p1[o] + p2[o] + p3[o] - centers[o] * a;
        yb[o] = y;
        ss += y * y;
    }
    __shared__ float red[4][KK];
    red[dg][k] = ss;
    __syncthreads();
    if (threadIdx.x < KK)
        g_red[(b * 16 + sl) * KK + k] = red[0][k] + red[1][k] + red[2][k] + red[3][k];
}

// ---------------------------------------------------------------------------
// Epilogue B: cnorm + scale. Global norm == sqrt(K)=8 -> fold 1/8.
// ---------------------------------------------------------------------------
__global__ void scale_kernel(float* __restrict__ out) {
    const int sl = blockIdx.x;
    const int b  = blockIdx.y;
    __shared__ float cns[KK];
    if (threadIdx.x < KK) {
        float s = 0.0f;
#pragma unroll
        for (int j = 0; j < 16; ++j) s += g_red[(b * 16 + j) * KK + threadIdx.x];
        cns[threadIdx.x] = 0.125f * rsqrtf(s);
    }
    __syncthreads();

    const float* yb = g_y + (size_t)b * DD * KK + (size_t)sl * 32 * KK;
    float* ob = out + (size_t)b * DD * KK + (size_t)sl * 32 * KK;
#pragma unroll
    for (int r = 0; r < 2; ++r) {
        int i = threadIdx.x + r * 256;
        int k4 = (i & 15) * 4;
        float4 v = *(const float4*)(yb + (size_t)i * 4);
        v.x *= cns[k4];
        v.y *= cns[k4 + 1];
        v.z *= cns[k4 + 2];
        v.w *= cns[k4 + 3];
        *(float4*)(ob + (size_t)i * 4) = v;
    }
}

// ---------------------------------------------------------------------------
extern "C" void kernel_launch(void* const* d_in, const int* in_sizes, int n_in,
                              void* d_out, int out_size) {
    const float* x       = (const float*)d_in[0];
    const float* w       = (const float*)d_in[1];
    const float* bias    = (const float*)d_in[2];
    const float* centers = (const float*)d_in[3];
    float* out = (float*)d_out;

    cudaFuncSetAttribute(fused_kernel,
                         cudaFuncAttributeMaxDynamicSharedMemorySize, SMEM_BYTES);

    fused_kernel<<<BB * CPB, THREADS, SMEM_BYTES>>>(x, w, bias);
    reduce_y_kernel<<<dim3(16, BB), 256>>>(centers);
    scale_kernel<<<dim3(16, BB), 256>>>(out);
}

// round 15
// speedup vs baseline: 1.3799x; 1.0132x over previous
#include <cuda_runtime.h>
#include <cuda_fp16.h>
#include <cstdint>
#include <math.h>

// ---------------- problem constants ----------------
#define BB 32
#define DD 512
#define KK 64
#define TNP 64              // pixels per tile
#define NNPIX 3136
#define NTILES 49           // 3136/64
#define CPB 4               // CTAs per batch
#define THREADS 512

// ---------------- smem byte offsets ----------------
// ws  : fp16 [64][520]  (1040B rows)                  66560
// xdn : fp16 [512][128B] XOR-swizzled                 65536
// xst : f32  [256][256B] staging (lower-half tile)    65536
// at  : f32  [64][68]                                 17408
// akp : fp16 [64] rows of 144B                         9216
// asr : f32  [8][72]                                   2304
#define WS_OFF    0
#define XDN_OFF   66560
#define XST_OFF   (XDN_OFF + 65536)            // 132096
#define AT_OFF    (XST_OFF + 65536)            // 197632
#define AKP_OFF   (AT_OFF + 17408)             // 215040
#define ASR_OFF   (AKP_OFF + 9216)             // 224256
#define SMEM_BYTES (ASR_OFF + 2304 + 16)       // 226576

// ---------------- device scratch ----------------
__device__ float g_part[BB * CPB * DD * KK];    // [cta][d][k]
__device__ float g_asum_part[BB * CPB * KK];    // [cta][k]
__device__ float g_y[BB * DD * KK];             // [b][d][k]
__device__ float g_red[BB * 16 * KK];           // sumsq slices [b][slice][k]

// m16n8k16 fp16 mma, f32 accum.
static __device__ __forceinline__ void mma_f16(float c[4],
        uint32_t a0, uint32_t a1, uint32_t a2, uint32_t a3,
        uint32_t b0, uint32_t b1) {
    asm volatile(
        "mma.sync.aligned.m16n8k16.row.col.f32.f16.f16.f32 "
        "{%0,%1,%2,%3}, {%4,%5,%6,%7}, {%8,%9}, {%0,%1,%2,%3};"
        : "+f"(c[0]), "+f"(c[1]), "+f"(c[2]), "+f"(c[3])
        : "r"(a0), "r"(a1), "r"(a2), "r"(a3), "r"(b0), "r"(b1));
}
#define LDSM4(r0, r1, r2, r3, addr) \
    asm volatile("ldmatrix.sync.aligned.m8n8.x4.shared.b16 {%0,%1,%2,%3}, [%4];" \
        : "=r"(r0), "=r"(r1), "=r"(r2), "=r"(r3) : "r"(addr))
#define LDSM4T(r0, r1, r2, r3, addr) \
    asm volatile("ldmatrix.sync.aligned.m8n8.x4.trans.shared.b16 {%0,%1,%2,%3}, [%4];" \
        : "=r"(r0), "=r"(r1), "=r"(r2), "=r"(r3) : "r"(addr))

static __device__ __forceinline__ uint32_t smem_u32(const void* p) {
    uint32_t a;
    asm("{ .reg .u64 t; cvta.to.shared.u64 t, %1; cvt.u32.u64 %0, t; }" : "=r"(a) : "l"(p));
    return a;
}
static __device__ __forceinline__ void cp16(uint32_t dst, const void* src) {
    asm volatile("cp.async.cg.shared.global [%0], [%1], 16;" :: "r"(dst), "l"(src));
}
#define CP_COMMIT() asm volatile("cp.async.commit_group;" ::: "memory")
#define CP_WAIT0()  asm volatile("cp.async.wait_group 0;" ::: "memory")

static __device__ __forceinline__ uint2 cvt_f4h(float4 v) {
    __half2 h0 = __floats2half2_rn(v.x, v.y);
    __half2 h1 = __floats2half2_rn(v.z, v.w);
    uint2 u;
    u.x = *(uint32_t*)&h0;
    u.y = *(uint32_t*)&h1;
    return u;
}

// ---------------------------------------------------------------------------
// Fused kernel. grid = 128 (b*4+q), block = 512, 1 CTA/SM.
// Lower half of next x tile: cp.async -> f32 stage (overlapped, register-free),
// converted to fp16 in the fill phase. Upper half: R11 register prefetch.
// ---------------------------------------------------------------------------
__global__ void __launch_bounds__(THREADS, 1) fused_kernel(
    const float* __restrict__ x,      // [B, D, N]
    const float* __restrict__ w,      // [K, D]
    const float* __restrict__ bias)   // [K]
{
    extern __shared__ char sm[];
    __half* ws    = (__half*)(sm + WS_OFF);
    char*   xdn   = sm + XDN_OFF;               // swizzled fp16 [512][128B]
    char*   xst   = sm + XST_OFF;               // f32 stage [256][256B]
    float*  at    = (float*)(sm + AT_OFF);      // [64][68]
    char*   akp   = sm + AKP_OFF;               // fp16 [64] rows of 144B
    float*  asred = (float*)(sm + ASR_OFF);     // [8][72]
    const uint32_t xdn_u = smem_u32(xdn);
    const uint32_t xst_u = smem_u32(xst);
    const uint32_t ws_u  = smem_u32(ws);
    const uint32_t akp_u = smem_u32(akp);

    const int tid  = threadIdx.x;
    const int wid  = tid >> 5;
    const int lane = tid & 31;
    const int g    = lane >> 2;
    const int tg   = lane & 3;
    const int b    = blockIdx.x >> 2;
    const int q    = blockIdx.x & 3;

    // ---- loader lane constants (128B swizzled xdn rows) ----------------------
    const int jj = tid & 15;
    const int r0 = tid >> 4;
    const uint32_t sts_off = (uint32_t)r0 * 128
        + ((uint32_t)((jj >> 1) ^ (r0 & 7)) * 16 + (uint32_t)(jj & 1) * 8);
    const uint32_t st_off = (uint32_t)r0 * 256 + (uint32_t)jj * 16;   // stage addr

    // ---- GEMM1 mapping: m-tile = 16 px (wid&3), n = 16 k at n0 ---------------
    const int p0 = (wid & 3) * 16;
    const int n0 = (wid >> 2) * 16;
    const float bias_a0 = bias[n0 + 2 * tg];
    const float bias_a1 = bias[n0 + 2 * tg + 1];
    const float bias_b0 = bias[n0 + 8 + 2 * tg];
    const float bias_b1 = bias[n0 + 8 + 2 * tg + 1];
    const uint32_t lmA1_off = (uint32_t)((lane & 7) + (lane >> 4) * 8) * 128
        + (uint32_t)((((wid & 3) * 2 + ((lane >> 3) & 1)) ^ (lane & 7)) * 16);
    const uint32_t lmB1 = ws_u
        + (uint32_t)((n0 + (lane & 7) + (lane >> 4) * 8) * 1040
                     + ((lane >> 3) & 1) * 16);

    // ---- GEMM2 mapping (retile): warp tile = 32 k x 64 d ----------------------
    const int kbw = (wid & 1) * 32;
    const int dbw = (wid >> 1) * 64;
    const uint32_t lmA2_0 = akp_u
        + (uint32_t)((kbw + (lane & 15)) * 144 + (lane >> 4) * 16);
    const uint32_t lmA2_1 = lmA2_0 + 16 * 144;
    const uint32_t lmB2_row = (uint32_t)(dbw + (lane & 7) + (lane >> 4) * 8) * 128;
    const uint32_t lc  = lane & 7;
    const uint32_t hi2 = (lane >> 3) & 1;

    // ---- convert w -> fp16 ws once --------------------------------------------
#pragma unroll
    for (int r = 0; r < 16; ++r) {
        int idx = tid + r * THREADS;
        int k = idx >> 7;
        int j = idx & 127;
        float4 v = *(const float4*)(w + (size_t)k * DD + j * 4);
        uint2 u = cvt_f4h(v);
        *(uint2*)((char*)ws + k * 1040 + j * 8) = u;
    }

    // persistent vlad^T accumulators [2 k-tiles][8 d-octets][4]
    float c2[2][8][4];
#pragma unroll
    for (int kt = 0; kt < 2; ++kt)
#pragma unroll
        for (int j = 0; j < 8; ++j)
#pragma unroll
            for (int r = 0; r < 4; ++r) c2[kt][j][r] = 0.0f;

    float asum_acc = 0.0f;
    const float* xg = x + (size_t)b * DD * NNPIX;

    // ---- prologue: cp.async lower half of tile q + pf upper half --------------
#pragma unroll
    for (int i = 0; i < 8; ++i)
        cp16(xst_u + st_off + (uint32_t)i * 8192,
             xg + (size_t)(r0 + i * 32) * NNPIX + q * TNP + jj * 4);
    CP_COMMIT();

    float4 pf[8];
#pragma unroll
    for (int i = 0; i < 8; ++i)
        pf[i] = *(const float4*)(xg + (size_t)(256 + r0 + i * 32) * NNPIX
                                 + q * TNP + jj * 4);

    int lt = 0;
    for (int t = q; t < NTILES; t += CPB, ++lt) {
        const bool has_next = (t + CPB < NTILES);

        __syncthreads();                       // (A) prev consumers of xdn/akp/xst done

        if (lt > 0 && tid < KK) {
            float s = 0.0f;
#pragma unroll
            for (int i = 0; i < 8; ++i) s += asred[i * 72 + tid];
            asum_acc += s;
        }

        // ---- fill xdn: upper from pf regs, lower from cp.async stage ---------
        CP_WAIT0();                            // this thread's staged lower half
#pragma unroll
        for (int i = 0; i < 8; ++i) {
            uint2 u = cvt_f4h(pf[i]);
            *(uint2*)(xdn + sts_off + (8 + i) * 4096) = u;   // rows 256+r0+i*32
        }
#pragma unroll
        for (int i = 0; i < 8; ++i) {
            float4 v = *(const float4*)(xst + st_off + i * 8192);
            uint2 u = cvt_f4h(v);
            *(uint2*)(xdn + sts_off + i * 4096) = u;         // rows r0+i*32
        }
        __syncthreads();                       // (B) xdn ready, stage consumed

        // ---- issue cp.async for next tile's lower half (register-free) -------
        if (has_next) {
#pragma unroll
            for (int i = 0; i < 8; ++i)
                cp16(xst_u + st_off + (uint32_t)i * 8192,
                     xg + (size_t)(r0 + i * 32) * NNPIX + (t + CPB) * TNP + jj * 4);
            CP_COMMIT();
        }

        // ---- GEMM1: logits^T[64px][64k] = x^T @ w^T ---------------------------
        {
            float c1a[4] = {0.f, 0.f, 0.f, 0.f};
            float c1b[4] = {0.f, 0.f, 0.f, 0.f};
            const uint32_t a_base = xdn_u + lmA1_off;
#pragma unroll
            for (int ks = 0; ks < 32; ++ks) {
                uint32_t a0, a1, a2, a3, b0, b1, b2, b3;
                LDSM4T(a0, a1, a2, a3, a_base + (uint32_t)ks * 2048);
                LDSM4(b0, b1, b2, b3, lmB1 + (uint32_t)ks * 32);
                mma_f16(c1a, a0, a1, a2, a3, b0, b1);
                mma_f16(c1b, a0, a1, a2, a3, b2, b3);
            }
            float* atp = at + (p0 + g) * 68;
            atp[n0 + 2 * tg]              = c1a[0] + bias_a0;
            atp[n0 + 2 * tg + 1]          = c1a[1] + bias_a1;
            atp[8 * 68 + n0 + 2 * tg]     = c1a[2] + bias_a0;
            atp[8 * 68 + n0 + 2 * tg + 1] = c1a[3] + bias_a1;
            atp[n0 + 8 + 2 * tg]              = c1b[0] + bias_b0;
            atp[n0 + 8 + 2 * tg + 1]          = c1b[1] + bias_b1;
            atp[8 * 68 + n0 + 8 + 2 * tg]     = c1b[2] + bias_b0;
            atp[8 * 68 + n0 + 8 + 2 * tg + 1] = c1b[3] + bias_b1;
        }
        __syncthreads();                       // (C) logits staged

        // ---- softmax over k per pixel -----------------------------------------
#pragma unroll
        for (int pp = 0; pp < 4; ++pp) {
            int p = wid * 4 + pp;
            float v0 = at[p * 68 + lane];
            float v1 = at[p * 68 + lane + 32];
            float m = fmaxf(v0, v1);
#pragma unroll
            for (int off = 16; off > 0; off >>= 1)
                m = fmaxf(m, __shfl_xor_sync(0xFFFFFFFFu, m, off));
            float e0 = __expf(v0 - m);
            float e1 = __expf(v1 - m);
            float s = e0 + e1;
#pragma unroll
            for (int off = 16; off > 0; off >>= 1)
                s += __shfl_xor_sync(0xFFFFFFFFu, s, off);
            float inv = 1.0f / s;
            *(__half*)(akp + lane * 144 + p * 2)        = __float2half_rn(e0 * inv);
            *(__half*)(akp + (lane + 32) * 144 + p * 2) = __float2half_rn(e1 * inv);
        }
        __syncthreads();                       // (D) alpha ready

        // ---- prefetch next tile upper half (lands during GEMM2) --------------
        if (has_next) {
#pragma unroll
            for (int i = 0; i < 8; ++i)
                pf[i] = *(const float4*)(xg + (size_t)(256 + r0 + i * 32) * NNPIX
                                         + (t + CPB) * TNP + jj * 4);
        }

        // ---- asum partials ------------------------------------------------------
        {
            int k = tid & 63;
            int grp = tid >> 6;
            uint4 u = *(const uint4*)(akp + k * 144 + grp * 16);
            float2 f0 = __half22float2(*(__half2*)&u.x);
            float2 f1 = __half22float2(*(__half2*)&u.y);
            float2 f2 = __half22float2(*(__half2*)&u.z);
            float2 f3 = __half22float2(*(__half2*)&u.w);
            asred[grp * 72 + k] = (f0.x + f0.y) + (f1.x + f1.y)
                                + (f2.x + f2.y) + (f3.x + f3.y);
        }

        // ---- GEMM2 (retile): vlad^T[32k x 64d per warp] += alpha @ x^T --------
#pragma unroll
        for (int s = 0; s < 4; ++s) {
            uint32_t aA0, aA1, aA2, aA3, aB0, aB1, aB2, aB3;
            LDSM4(aA0, aA1, aA2, aA3, lmA2_0 + (uint32_t)s * 32);
            LDSM4(aB0, aB1, aB2, aB3, lmA2_1 + (uint32_t)s * 32);
            const uint32_t swoff = (((uint32_t)s * 2 + hi2) ^ lc) * 16;
            const uint32_t bbase = xdn_u + lmB2_row + swoff;
#pragma unroll
            for (int j2 = 0; j2 < 4; ++j2) {
                uint32_t b0, b1, b2, b3;
                LDSM4(b0, b1, b2, b3, bbase + (uint32_t)j2 * 2048);
                mma_f16(c2[0][2 * j2],     aA0, aA1, aA2, aA3, b0, b1);
                mma_f16(c2[0][2 * j2 + 1], aA0, aA1, aA2, aA3, b2, b3);
                mma_f16(c2[1][2 * j2],     aB0, aB1, aB2, aB3, b0, b1);
                mma_f16(c2[1][2 * j2 + 1], aB0, aB1, aB2, aB3, b2, b3);
            }
        }
    }

    __syncthreads();
    if (tid < KK) {
        float s = 0.0f;
#pragma unroll
        for (int i = 0; i < 8; ++i) s += asred[i * 72 + tid];
        g_asum_part[blockIdx.x * KK + tid] = asum_acc + s;
    }

    // ---- epilogue: transpose-stage vlad^T -> g_part[cta][d][k] ----------------
    float* stage = (float*)xdn;                // [128][72] f32
    float* dstb = g_part + (size_t)blockIdx.x * DD * KK;
    const int dloc = ((wid >> 1) & 1) * 64;
    for (int chunk = 0; chunk < 4; ++chunk) {
        __syncthreads();
        if ((wid >> 2) == chunk) {
#pragma unroll
            for (int kt = 0; kt < 2; ++kt) {
                int kcol = kbw + kt * 16 + g;
#pragma unroll
                for (int j = 0; j < 8; ++j) {
                    int dl = dloc + j * 8 + 2 * tg;
                    stage[dl * 72 + kcol]           = c2[kt][j][0];
                    stage[(dl + 1) * 72 + kcol]     = c2[kt][j][1];
                    stage[dl * 72 + kcol + 8]       = c2[kt][j][2];
                    stage[(dl + 1) * 72 + kcol + 8] = c2[kt][j][3];
                }
            }
        }
        __syncthreads();
        float* dst = dstb + (size_t)chunk * 128 * KK;
#pragma unroll
        for (int r = 0; r < 4; ++r) {
            int i = tid + r * THREADS;
            int dl = i >> 4;
            int k4 = (i & 15) * 4;
            float4 v = *(float4*)&stage[dl * 72 + k4];
            *(float4*)&dst[(size_t)dl * KK + k4] = v;
        }
    }
}

// ---------------------------------------------------------------------------
// Epilogue A: y = sum_q part - centers*asum ; per-slice sumsq partials.
// ---------------------------------------------------------------------------
__global__ void reduce_y_kernel(const float* __restrict__ centers) {
    const int sl = blockIdx.x;
    const int b  = blockIdx.y;
    const int k  = threadIdx.x & 63;
    const int dg = threadIdx.x >> 6;

    float a = g_asum_part[(b * 4 + 0) * KK + k]
            + g_asum_part[(b * 4 + 1) * KK + k]
            + g_asum_part[(b * 4 + 2) * KK + k]
            + g_asum_part[(b * 4 + 3) * KK + k];

    const float* p0 = g_part + (size_t)(b * 4 + 0) * DD * KK;
    const float* p1 = g_part + (size_t)(b * 4 + 1) * DD * KK;
    const float* p2 = g_part + (size_t)(b * 4 + 2) * DD * KK;
    const float* p3 = g_part + (size_t)(b * 4 + 3) * DD * KK;
    float* yb = g_y + (size_t)b * DD * KK;

    float ss = 0.0f;
#pragma unroll
    for (int i = 0; i < 8; ++i) {
        int d = sl * 32 + dg * 8 + i;
        size_t o = (size_t)d * KK + k;
        float y = p0[o] + p1[o] + p2[o] + p3[o] - centers[o] * a;
        yb[o] = y;
        ss += y * y;
    }
    __shared__ float red[4][KK];
    red[dg][k] = ss;
    __syncthreads();
    if (threadIdx.x < KK)
        g_red[(b * 16 + sl) * KK + k] = red[0][k] + red[1][k] + red[2][k] + red[3][k];
}

// ---------------------------------------------------------------------------
// Epilogue B: cnorm + scale. Global norm == sqrt(K)=8 -> fold 1/8.
// ---------------------------------------------------------------------------
__global__ void scale_kernel(float* __restrict__ out) {
    const int sl = blockIdx.x;
    const int b  = blockIdx.y;
    __shared__ float cns[KK];
    if (threadIdx.x < KK) {
        float s = 0.0f;
#pragma unroll
        for (int j = 0; j < 16; ++j) s += g_red[(b * 16 + j) * KK + threadIdx.x];
        cns[threadIdx.x] = 0.125f * rsqrtf(s);
    }
    __syncthreads();

    const float* yb = g_y + (size_t)b * DD * KK + (size_t)sl * 32 * KK;
    float* ob = out + (size_t)b * DD * KK + (size_t)sl * 32 * KK;
#pragma unroll
    for (int r = 0; r < 2; ++r) {
        int i = threadIdx.x + r * 256;
        int k4 = (i & 15) * 4;
        float4 v = *(const float4*)(yb + (size_t)i * 4);
        v.x *= cns[k4];
        v.y *= cns[k4 + 1];
        v.z *= cns[k4 + 2];
        v.w *= cns[k4 + 3];
        *(float4*)(ob + (size_t)i * 4) = v;
    }
}

// ---------------------------------------------------------------------------
extern "C" void kernel_launch(void* const* d_in, const int* in_sizes, int n_in,
                              void* d_out, int out_size) {
    const float* x       = (const float*)d_in[0];
    const float* w       = (const float*)d_in[1];
    const float* bias    = (const float*)d_in[2];
    const float* centers = (const float*)d_in[3];
    float* out = (float*)d_out;

    cudaFuncSetAttribute(fused_kernel,
                         cudaFuncAttributeMaxDynamicSharedMemorySize, SMEM_BYTES);

    fused_kernel<<<BB * CPB, THREADS, SMEM_BYTES>>>(x, w, bias);
    reduce_y_kernel<<<dim3(16, BB), 256>>>(centers);
    scale_kernel<<<dim3(16, BB), 256>>>(out);
}